// round 16
// baseline (speedup 1.0000x reference)
#include <cuda_runtime.h>
#include <cstdint>

// SparseToDense via single-pass fixed-capacity bucket partition (no histogram,
// no scan). Partition processes 4 points/thread for MLP; slots are 80B
// (payload + local id fused) at CAP=64 for dense row-friendly writes. Scatter
// reads its bin's slots coalesced, count-gated smem accumulate, cp.async.bulk
// writeback. Overflow (>CAP pts/bin, ~400 pts expected) applied exactly by a
// post-pass with red.global.add.
// out[b][f][x][y][z] += feats[n][f], out = (4,16,128,128,128) f32.

#define VOL    (128 * 128 * 128)
#define FEATS  16
#define NBINS  32768            // (b:2, x:7, y/2:6)
#define BLKV   256              // voxels per bin
#define BLKT   128              // threads per scatter CTA
#define CAP    64               // slots per bin (mean 46.7, sigma 6.8)
#define OVMAX  262144

__device__ int g_cnt[NBINS];              // zero at load; scatter re-zeroes
__device__ int g_ovcnt;                   // zero at load; overflow re-zeroes
__device__ int g_ovlist[OVMAX];
__device__ float4 g_fslot[(size_t)NBINS * CAP * 5];   // 168MB: [f0..f3, aux]

__device__ __forceinline__ bool decode(const int4 c, unsigned& bin, unsigned& local)
{
    const unsigned x = (unsigned)c.y;
    const unsigned y = (unsigned)c.z;
    const unsigned z = (unsigned)c.w;
    if ((x >= 128u) | (y >= 128u) | (z >= 128u)) return false;
    bin   = ((((unsigned)c.x << 7) | x) << 6) | (y >> 1);   // (b,x,y/2)
    local = ((y & 1u) << 7) | z;                            // 0..255
    return true;
}

// Single-pass partition, 4 consecutive points per thread for MLP.
__global__ void __launch_bounds__(256)
partition_kernel(const int4* __restrict__ coords,
                 const float4* __restrict__ feats, int n)
{
    const int stride = gridDim.x * blockDim.x * 4;
    for (int base = (blockIdx.x * blockDim.x + threadIdx.x) * 4; base < n;
         base += stride) {

        int4  c[4];
        bool  valid[4];
        unsigned bin[4], local[4];
        float4 f[4][4];

        #pragma unroll
        for (int k = 0; k < 4; k++) {
            const int idx = base + k;
            valid[k] = (idx < n);
            if (valid[k]) c[k] = __ldg(&coords[idx]);
        }
        #pragma unroll
        for (int k = 0; k < 4; k++)
            if (valid[k]) valid[k] = decode(c[k], bin[k], local[k]);

        // Independent feat loads for all valid points: high MLP.
        #pragma unroll
        for (int k = 0; k < 4; k++) {
            if (valid[k]) {
                const float4* fp = feats + (size_t)(base + k) * 4;
                f[k][0] = __ldg(fp + 0);
                f[k][1] = __ldg(fp + 1);
                f[k][2] = __ldg(fp + 2);
                f[k][3] = __ldg(fp + 3);
            }
        }

        // Independent atomics, then dependent slot stores.
        int pos[4];
        #pragma unroll
        for (int k = 0; k < 4; k++)
            if (valid[k]) pos[k] = atomicAdd(&g_cnt[bin[k]], 1);

        #pragma unroll
        for (int k = 0; k < 4; k++) {
            if (!valid[k]) continue;
            if (pos[k] < CAP) {
                float4* dst = g_fslot + ((size_t)bin[k] * CAP + pos[k]) * 5;
                dst[0] = f[k][0];
                dst[1] = f[k][1];
                dst[2] = f[k][2];
                dst[3] = f[k][3];
                dst[4] = make_float4(__uint_as_float(local[k]), 0.f, 0.f, 0.f);
            } else {
                const int ov = atomicAdd(&g_ovcnt, 1);
                if (ov < OVMAX) g_ovlist[ov] = base + k;
            }
        }
    }
}

__global__ void __launch_bounds__(BLKT)
scatter_kernel(float* __restrict__ out)
{
    __shared__ __align__(16) float acc[FEATS * BLKV];   // [f][256], 1KB per f
    __shared__ int cnt[BLKV];

    const unsigned bin = blockIdx.x;
    const int tid = threadIdx.x;
    int npts = g_cnt[bin];
    if (npts > CAP) npts = CAP;          // overflow points applied later

    #pragma unroll
    for (int k = 0; k < FEATS * BLKV / 4 / BLKT; k++)   // 8 iters
        *(float4*)&acc[(k * BLKT + tid) * 4] = make_float4(0.f, 0.f, 0.f, 0.f);
    cnt[2 * tid]     = 0;
    cnt[2 * tid + 1] = 0;

    // Fused single-pass (npts <= CAP <= BLKT): loads issued before the count
    // barrier; slot reads are coalesced within the bin region.
    const bool have = (tid < npts);
    unsigned local = 0;
    float4 f0, f1, f2, f3;
    if (have) {
        const float4* fp = g_fslot + ((size_t)bin * CAP + tid) * 5;
        f0 = __ldg(fp + 0);
        f1 = __ldg(fp + 1);
        f2 = __ldg(fp + 2);
        f3 = __ldg(fp + 3);
        local = __float_as_uint(__ldg(fp + 4).x) & 255u;
    }
    __syncthreads();                     // cnt[] zeros visible
    if (have) atomicAdd(&cnt[local], 1);
    __syncthreads();

    if (have) {
        float v[16] = { f0.x, f0.y, f0.z, f0.w,
                        f1.x, f1.y, f1.z, f1.w,
                        f2.x, f2.y, f2.z, f2.w,
                        f3.x, f3.y, f3.z, f3.w };
        if (cnt[local] == 1) {
            #pragma unroll
            for (int f = 0; f < FEATS; f++)
                acc[f * BLKV + local] = v[f];
        } else {
            #pragma unroll
            for (int f = 0; f < FEATS; f++)
                atomicAdd(&acc[f * BLKV + local], v[f]);
        }
    }
    __syncthreads();

    // ---- bulk async writeback: 16 contiguous 1KB chunks, TMA engine ----
    if (tid == 0) {
        asm volatile("fence.proxy.async.shared::cta;" ::: "memory");

        const unsigned b = bin >> 13;
        float* base = out + (size_t)b * FEATS * VOL + ((size_t)(bin & 8191u) << 8);

        uint32_t sa;
        asm("{ .reg .u64 t; cvta.to.shared.u64 t, %1; cvt.u32.u64 %0, t; }"
            : "=r"(sa) : "l"(acc));

        #pragma unroll
        for (int f = 0; f < FEATS; f++) {
            asm volatile(
                "cp.async.bulk.global.shared::cta.bulk_group [%0], [%1], %2;"
                :: "l"(base + (size_t)f * VOL),
                   "r"(sa + f * BLKV * 4),
                   "n"(BLKV * 4)
                : "memory");
        }
        asm volatile("cp.async.bulk.commit_group;" ::: "memory");
        asm volatile("cp.async.bulk.wait_group.read 0;" ::: "memory");

        g_cnt[bin] = 0;                  // clean for next graph replay
    }
}

// Apply overflow points exactly with fire-and-forget atomics on the written
// dense output; then reset the overflow counter.
__global__ void __launch_bounds__(256)
overflow_kernel(const int4* __restrict__ coords,
                const float4* __restrict__ feats, float* __restrict__ out)
{
    const int tid = blockIdx.x * blockDim.x + threadIdx.x;
    int nov = g_ovcnt;
    if (nov > OVMAX) nov = OVMAX;

    for (int t = tid; t < nov; t += gridDim.x * blockDim.x) {
        const int i = g_ovlist[t];
        const int4 c = __ldg(&coords[i]);
        const unsigned lin = ((unsigned)c.y << 14) | ((unsigned)c.z << 7) | (unsigned)c.w;
        float* base = out + (size_t)c.x * (FEATS * (size_t)VOL) + lin;

        const float4* fp = feats + (size_t)i * 4;
        float4 f0 = __ldg(fp + 0);
        float4 f1 = __ldg(fp + 1);
        float4 f2 = __ldg(fp + 2);
        float4 f3 = __ldg(fp + 3);
        float v[16] = { f0.x, f0.y, f0.z, f0.w,
                        f1.x, f1.y, f1.z, f1.w,
                        f2.x, f2.y, f2.z, f2.w,
                        f3.x, f3.y, f3.z, f3.w };
        #pragma unroll
        for (int f = 0; f < FEATS; f++)
            asm volatile("red.global.add.f32 [%0], %1;"
                         :: "l"(base + (size_t)f * VOL), "f"(v[f]) : "memory");
    }
    if (blockIdx.x == 0 && threadIdx.x == 0) g_ovcnt = 0;  // clean for replay
}

extern "C" void kernel_launch(void* const* d_in, const int* in_sizes, int n_in,
                              void* d_out, int out_size)
{
    const int4*   coords = (const int4*)d_in[0];
    const float4* feats  = (const float4*)d_in[1];
    float*        out    = (float*)d_out;

    const int n = in_sizes[0] / 4;

    partition_kernel<<<1024, 256>>>(coords, feats, n);  // launch 1
    scatter_kernel<<<NBINS, BLKT>>>(out);               // launch 2
    overflow_kernel<<<32, 256>>>(coords, feats, out);   // launch 3
}